// round 17
// baseline (speedup 1.0000x reference)
#include <cuda_runtime.h>
#include <cuda_fp16.h>
#include <math.h>
#include <stdint.h>

// ---------------- problem constants ----------------
#define T_TOK 16384
#define DM    1024
#define HID   512
#define NE    16
#define TOPK  2

// ---------------- tiling ----------------
#define BMT 128
#define BNT 128
#define MTILES 272
#define PAD_ROWS (MTILES * BMT)

// shared tile geometry (BK=64, 2 stages) for both FFN kernels
#define BK1 64
#define T1STR 36                       // words per 64-half row (32 data + 4 pad)
#define T1ROWB (T1STR * 4)             // 144 B
#define T1W (128 * T1STR)              // 4608 words per 128x64-half tile
#define F1_STAGE (3 * T1W)             // A + G + U
#define F2_STAGE (2 * T1W)             // A + B
#define F1_SMEM (2 * F1_STAGE * 4)     // 110592 B
#define F2_SMEM (2 * F2_STAGE * 4)     // 73728 B

// ---------------- static scratch ----------------
__device__ int   g_counts[NE];
__device__ int   g_cursor[NE];
__device__ int   g_off[NE];
__device__ int   g_tile_e[MTILES];
__device__ int   g_tile_base[MTILES];
__device__ int   g_tok_idx[T_TOK * TOPK];
__device__ float g_tok_w[T_TOK * TOPK];
__device__ int   g_row_tok[PAD_ROWS];
__device__ float g_row_w[PAD_ROWS];
__device__ __align__(16) __half g_Xh[(size_t)T_TOK * DM];
__device__ __align__(16) __half g_gph[(size_t)NE * HID * DM];   // [e][n][k]
__device__ __align__(16) __half g_uph[(size_t)NE * HID * DM];   // [e][n][k]
__device__ __align__(16) __half g_dph[(size_t)NE * DM * HID];   // [e][n][k]
__device__ __align__(16) __half g_H[(size_t)PAD_ROWS * HID];

// ---------------- helpers ----------------
__device__ __forceinline__ uint32_t smem_u32(const void* p) {
    uint32_t a;
    asm("{ .reg .u64 t; cvta.to.shared.u64 t, %1; cvt.u32.u64 %0, t; }" : "=r"(a) : "l"(p));
    return a;
}

__device__ __forceinline__ void mma16(float c[4], const uint32_t a[4],
                                      uint32_t b0, uint32_t b1) {
    asm volatile(
        "mma.sync.aligned.m16n8k16.row.col.f32.f16.f16.f32 "
        "{%0,%1,%2,%3}, {%4,%5,%6,%7}, {%8,%9}, {%0,%1,%2,%3};"
        : "+f"(c[0]), "+f"(c[1]), "+f"(c[2]), "+f"(c[3])
        : "r"(a[0]), "r"(a[1]), "r"(a[2]), "r"(a[3]), "r"(b0), "r"(b1));
}

__device__ __forceinline__ void ldsm4(uint32_t r[4], uint32_t addr) {
    asm volatile("ldmatrix.sync.aligned.m8n8.x4.shared.b16 {%0,%1,%2,%3}, [%4];"
                 : "=r"(r[0]), "=r"(r[1]), "=r"(r[2]), "=r"(r[3]) : "r"(addr));
}

#define CP16(dst, src) \
    asm volatile("cp.async.cg.shared.global [%0], [%1], 16;" :: "r"(dst), "l"(src))
#define CP16Z(dst, src, sz) \
    asm volatile("cp.async.cg.shared.global [%0], [%1], 16, %2;" :: "r"(dst), "l"(src), "r"(sz))
#define CP_COMMIT() asm volatile("cp.async.commit_group;" ::: "memory")
#define CP_WAIT(n)  asm volatile("cp.async.wait_group %0;" :: "n"(n) : "memory")

// ---------------- routing kernels ----------------
__global__ void init_kernel() {
    int i = threadIdx.x;
    if (i < NE) g_counts[i] = 0;
}

// gate, 4 tokens per warp: gw loads amortized 4x; all loads coalesced LDG.128
__global__ void gate_kernel(const float* __restrict__ x,
                            const float* __restrict__ gw,
                            const float* __restrict__ gb) {
    int gid = blockIdx.x * blockDim.x + threadIdx.x;
    int warp = gid >> 5, lane = gid & 31;
    int t0 = warp * 4;
    if (t0 >= T_TOK) return;
    int q = lane & 3, g = lane >> 2;

    const float4* gw4 = (const float4*)gw;
    float4 acc[4];
#pragma unroll
    for (int tt = 0; tt < 4; tt++) acc[tt] = make_float4(0.f, 0.f, 0.f, 0.f);

#pragma unroll 2
    for (int it = 0; it < 32; it++) {
        int d = it * 32 + g * 4;
        float4 w4[4];
#pragma unroll
        for (int i = 0; i < 4; i++) w4[i] = gw4[(size_t)(d + i) * 4 + q];
#pragma unroll
        for (int tt = 0; tt < 4; tt++) {
            const float* xr = x + (size_t)(t0 + tt) * DM;
            float4 x4 = *(const float4*)(xr + d);
            if (q == 0) {
                half2 a = __floats2half2_rn(x4.x, x4.y);
                half2 b = __floats2half2_rn(x4.z, x4.w);
                uint2 pk = make_uint2(*reinterpret_cast<uint32_t*>(&a),
                                      *reinterpret_cast<uint32_t*>(&b));
                *(uint2*)(g_Xh + (size_t)(t0 + tt) * DM + d) = pk;
            }
#pragma unroll
            for (int i = 0; i < 4; i++) {
                float xv = (&x4.x)[i];
                acc[tt].x = fmaf(xv, w4[i].x, acc[tt].x);
                acc[tt].y = fmaf(xv, w4[i].y, acc[tt].y);
                acc[tt].z = fmaf(xv, w4[i].z, acc[tt].z);
                acc[tt].w = fmaf(xv, w4[i].w, acc[tt].w);
            }
        }
    }

#pragma unroll
    for (int tt = 0; tt < 4; tt++) {
        int t = t0 + tt;
        float4 a = acc[tt];
#pragma unroll
        for (int off = 4; off < 32; off <<= 1) {
            a.x += __shfl_xor_sync(0xffffffffu, a.x, off);
            a.y += __shfl_xor_sync(0xffffffffu, a.y, off);
            a.z += __shfl_xor_sync(0xffffffffu, a.z, off);
            a.w += __shfl_xor_sync(0xffffffffu, a.w, off);
        }
        float s[NE];
#pragma unroll
        for (int src = 0; src < 4; src++) {
            s[src * 4 + 0] = __shfl_sync(0xffffffffu, a.x, src);
            s[src * 4 + 1] = __shfl_sync(0xffffffffu, a.y, src);
            s[src * 4 + 2] = __shfl_sync(0xffffffffu, a.z, src);
            s[src * 4 + 3] = __shfl_sync(0xffffffffu, a.w, src);
        }
        if (lane == 0) {
            float mx = -1e30f;
#pragma unroll
            for (int e = 0; e < NE; e++) { s[e] += gb[e]; mx = fmaxf(mx, s[e]); }
            float sum = 0.f;
#pragma unroll
            for (int e = 0; e < NE; e++) { s[e] = expf(s[e] - mx); sum += s[e]; }
            int i1 = 0; float v1 = -1.f;
#pragma unroll
            for (int e = 0; e < NE; e++) if (s[e] > v1) { v1 = s[e]; i1 = e; }
            int i2 = 0; float v2 = -1.f;
#pragma unroll
            for (int e = 0; e < NE; e++) if (e != i1 && s[e] > v2) { v2 = s[e]; i2 = e; }
            float p1 = v1 / sum, p2 = v2 / sum;
            float den = p1 + p2 + 1e-9f;
            g_tok_idx[2 * t + 0] = i1; g_tok_w[2 * t + 0] = p1 / den;
            g_tok_idx[2 * t + 1] = i2; g_tok_w[2 * t + 1] = p2 / den;
            atomicAdd(&g_counts[i1], 1);
            atomicAdd(&g_counts[i2], 1);
        }
    }
}

// serial offsets + tile table only
__global__ void scan_kernel() {
    int off = 0, tile = 0;
    for (int e = 0; e < NE; e++) {
        g_off[e] = off; g_cursor[e] = 0;
        int c = g_counts[e];
        int nt = (c + BMT - 1) / BMT;
        for (int j = 0; j < nt; j++) {
            g_tile_e[tile] = e;
            g_tile_base[tile] = off + j * BMT;
            tile++;
        }
        off += nt * BMT;
    }
    for (; tile < MTILES; tile++) g_tile_e[tile] = -1;
}

// parallel padding fill
__global__ void pad_kernel() {
    int r = blockIdx.x * blockDim.x + threadIdx.x;
    if (r >= PAD_ROWS) return;
#pragma unroll
    for (int e = 0; e < NE; e++) {
        int o = g_off[e];
        int c = g_counts[e];
        int end = o + ((c + BMT - 1) / BMT) * BMT;
        if (r >= o + c && r < end) {
            g_row_tok[r] = -1;
            g_row_w[r] = 0.f;
            return;
        }
    }
}

__global__ void scatter_kernel() {
    int t = blockIdx.x * blockDim.x + threadIdx.x;
    if (t >= T_TOK) return;
#pragma unroll
    for (int k = 0; k < TOPK; k++) {
        int e = g_tok_idx[2 * t + k];
        int pos = g_off[e] + atomicAdd(&g_cursor[e], 1);
        g_row_tok[pos] = t;
        g_row_w[pos] = g_tok_w[2 * t + k];
    }
}

__global__ void zero_kernel(float* out, long n) {
    long i = blockIdx.x * (long)blockDim.x + threadIdx.x;
    long st = (long)gridDim.x * blockDim.x;
    for (; i < n; i += st) out[i] = 0.f;
}

__global__ void aux_kernel(float* out, long out_size) {
    if (blockIdx.x == 0 && threadIdx.x == 0) {
        const float cap = 1.25f * (float)(T_TOK * TOPK) / (float)NE;
        float sum = 0.f;
        for (int e = 0; e < NE; e++) {
            float l = (float)g_counts[e] - cap;
            if (l > 0.f) sum += l;
        }
        float aux = 0.01f * sum / (float)NE / (float)T_TOK;
        long TD = (long)T_TOK * DM;
        if (out_size > TD) out[TD] = aux;
    }
}

// all three weights: [e][K][N] float -> [e][N][K] half
__global__ void convert_weights(const float* __restrict__ gp,
                                const float* __restrict__ up,
                                const float* __restrict__ dp) {
    __shared__ float tile[32][33];
    int z = blockIdx.z;
    const float* src; __half* dst; int K, N;
    if (z < NE)          { src = gp + (size_t)z * DM * HID;        dst = g_gph + (size_t)z * HID * DM;        K = DM;  N = HID; }
    else if (z < 2 * NE) { src = up + (size_t)(z - NE) * DM * HID; dst = g_uph + (size_t)(z - NE) * HID * DM; K = DM;  N = HID; }
    else                 { src = dp + (size_t)(z - 2 * NE) * HID * DM; dst = g_dph + (size_t)(z - 2 * NE) * DM * HID; K = HID; N = DM; }
    int k0 = blockIdx.y * 32, n0 = blockIdx.x * 32;
    if (k0 >= K || n0 >= N) return;
    int tx = threadIdx.x, ty = threadIdx.y;
#pragma unroll
    for (int i = 0; i < 32; i += 8)
        tile[ty + i][tx] = src[(size_t)(k0 + ty + i) * N + n0 + tx];
    __syncthreads();
#pragma unroll
    for (int i = 0; i < 32; i += 8)
        dst[(size_t)(n0 + ty + i) * K + k0 + tx] = __float2half_rn(tile[tx][ty + i]);
}

// ============ FFN stage 1: H = (X@gp + b) * silu(X@up + b) ============
__global__ void __launch_bounds__(512, 1)
ffn1_mma(const float* __restrict__ gp_b, const float* __restrict__ up_b) {
    int mt = blockIdx.x;
    int e = g_tile_e[mt];
    if (e < 0) return;
    int rb = g_tile_base[mt];
    int n0 = blockIdx.y * BNT;

    extern __shared__ uint32_t sm[];
    __shared__ int s_toks[BMT];

    int tid = threadIdx.x, lane = tid & 31, wid = tid >> 5;
    int wm = wid & 3, wn = wid >> 2;
    if (tid < BMT) s_toks[tid] = g_row_tok[rb + tid];
    __syncthreads();

    uint32_t sbase = smem_u32(sm);
    const __half* gpe = g_gph + (size_t)e * HID * DM;
    const __half* upe = g_uph + (size_t)e * HID * DM;

    const __half* asrc[2]; uint32_t asz[2], tdst[2];
    const __half* gsrc[2]; const __half* usrc[2];
#pragma unroll
    for (int j = 0; j < 2; j++) {
        int p = tid + 512 * j;
        int row = p >> 3, pc = p & 7;
        int tok = s_toks[row];
        asrc[j] = g_Xh + (size_t)(tok >= 0 ? tok : 0) * DM + pc * 8;
        asz[j]  = (tok >= 0) ? 16u : 0u;
        gsrc[j] = gpe + (size_t)(n0 + row) * DM + pc * 8;
        usrc[j] = upe + (size_t)(n0 + row) * DM + pc * 8;
        tdst[j] = (uint32_t)(row * T1STR + pc * 4) * 4u;
    }

    float cg[2][4][4] = {}, cu[2][4][4] = {};
    uint32_t a_off = (uint32_t)((wm * 32 + (lane & 15)) * T1ROWB + (lane >> 4) * 16);
    uint32_t b_off = (uint32_t)((wn * 32 + ((lane >> 4) & 1) * 8 + (lane & 7)) * T1ROWB
                                + ((lane >> 3) & 1) * 16);

    const int NC = DM / BK1;   // 16
    {
#pragma unroll
        for (int j = 0; j < 2; j++) {
            CP16Z(sbase + tdst[j], asrc[j], asz[j]);
            CP16(sbase + T1W * 4 + tdst[j], gsrc[j]);
            CP16(sbase + 2 * T1W * 4 + tdst[j], usrc[j]);
        }
        CP_COMMIT();
    }

    for (int c = 0; c < NC; ++c) {
        CP_WAIT(0);
        __syncthreads();
        int cn = c + 1;
        if (cn < NC) {
            int k0 = cn * BK1;
            uint32_t stg = sbase + (uint32_t)((cn & 1) * F1_STAGE * 4);
#pragma unroll
            for (int j = 0; j < 2; j++) {
                CP16Z(stg + tdst[j], asrc[j] + k0, asz[j]);
                CP16(stg + T1W * 4 + tdst[j], gsrc[j] + k0);
                CP16(stg + 2 * T1W * 4 + tdst[j], usrc[j] + k0);
            }
        }
        CP_COMMIT();
        uint32_t Ab = sbase + (uint32_t)((c & 1) * F1_STAGE * 4);
        uint32_t Gb = Ab + T1W * 4;
        uint32_t Ub = Gb + T1W * 4;
#pragma unroll
        for (int s = 0; s < 4; s++) {
            uint32_t so = (uint32_t)(s * 32);
            uint32_t a[2][4], gf[2][4], uf[2][4];
#pragma unroll
            for (int mi = 0; mi < 2; mi++)
                ldsm4(a[mi], Ab + a_off + (uint32_t)(mi * 16 * T1ROWB) + so);
#pragma unroll
            for (int pi = 0; pi < 2; pi++) {
                ldsm4(gf[pi], Gb + b_off + (uint32_t)(pi * 16 * T1ROWB) + so);
                ldsm4(uf[pi], Ub + b_off + (uint32_t)(pi * 16 * T1ROWB) + so);
            }
#pragma unroll
            for (int pi = 0; pi < 2; pi++) {
#pragma unroll
                for (int h = 0; h < 2; h++) {
                    int ni = 2 * pi + h;
                    uint32_t g0 = gf[pi][2 * h], g1 = gf[pi][2 * h + 1];
                    uint32_t u0 = uf[pi][2 * h], u1 = uf[pi][2 * h + 1];
                    mma16(cg[0][ni], a[0], g0, g1);
                    mma16(cg[1][ni], a[1], g0, g1);
                    mma16(cu[0][ni], a[0], u0, u1);
                    mma16(cu[1][ni], a[1], u0, u1);
                }
            }
        }
    }

    const float* gpb = gp_b + e * HID + n0;
    const float* upb = up_b + e * HID + n0;
    int rrow = rb + wm * 32 + (lane >> 2);
    int cbase = wn * 32 + 2 * (lane & 3);
#pragma unroll
    for (int ni = 0; ni < 4; ni++) {
        int col = cbase + ni * 8;
        float gb0 = gpb[col], gb1 = gpb[col + 1];
        float ub0 = upb[col], ub1 = upb[col + 1];
#pragma unroll
        for (int mi = 0; mi < 2; mi++) {
            int r0 = rrow + mi * 16;
            float g, u, h0, h1;
            g = cg[mi][ni][0] + gb0; u = cu[mi][ni][0] + ub0;
            h0 = g * (u / (1.f + expf(-u)));
            g = cg[mi][ni][1] + gb1; u = cu[mi][ni][1] + ub1;
            h1 = g * (u / (1.f + expf(-u)));
            *(half2*)(g_H + (size_t)r0 * HID + n0 + col) = __floats2half2_rn(h0, h1);
            g = cg[mi][ni][2] + gb0; u = cu[mi][ni][2] + ub0;
            h0 = g * (u / (1.f + expf(-u)));
            g = cg[mi][ni][3] + gb1; u = cu[mi][ni][3] + ub1;
            h1 = g * (u / (1.f + expf(-u)));
            *(half2*)(g_H + (size_t)(r0 + 8) * HID + n0 + col) = __floats2half2_rn(h0, h1);
        }
    }
}

// ============ FFN stage 2: out[tok] += w * (H @ dp_w + dp_b) ============
__global__ void __launch_bounds__(512, 1)
ffn2_mma(const float* __restrict__ dp_b, float* __restrict__ out) {
    int mt = blockIdx.x;
    int e = g_tile_e[mt];
    if (e < 0) return;
    int rb = g_tile_base[mt];
    int n0 = blockIdx.y * BNT;

    extern __shared__ uint32_t sm2[];
    __shared__ int   s_toks[BMT];
    __shared__ float s_wts[BMT];

    int tid = threadIdx.x, lane = tid & 31, wid = tid >> 5;
    int wm = wid & 3, wn = wid >> 2;
    if (tid < BMT) {
        s_toks[tid] = g_row_tok[rb + tid];
        s_wts[tid]  = g_row_w[rb + tid];
    }
    __syncthreads();

    uint32_t sbase = smem_u32(sm2);
    const __half* dpe = g_dph + (size_t)e * DM * HID;   // [n][k]

    const __half* asrc[2]; const __half* bsrc[2]; uint32_t tdst[2];
#pragma unroll
    for (int j = 0; j < 2; j++) {
        int p = tid + 512 * j;
        int row = p >> 3, pc = p & 7;
        asrc[j] = g_H + (size_t)(rb + row) * HID + pc * 8;
        bsrc[j] = dpe + (size_t)(n0 + row) * HID + pc * 8;
        tdst[j] = (uint32_t)(row * T1STR + pc * 4) * 4u;
    }

    float ca[2][4][4] = {};
    uint32_t a_off = (uint32_t)((wm * 32 + (lane & 15)) * T1ROWB + (lane >> 4) * 16);
    uint32_t b_off = (uint32_t)((wn * 32 + ((lane >> 4) & 1) * 8 + (lane & 7)) * T1ROWB
                                + ((lane >> 3) & 1) * 16);

    const int NC = HID / BK1;   // 8
    {
#pragma unroll
        for (int j = 0; j < 2; j++) {
            CP16(sbase + tdst[j], asrc[j]);
            CP16(sbase + T1W * 4 + tdst[j], bsrc[j]);
        }
        CP_COMMIT();
    }

    for (int c = 0; c < NC; ++c) {
        CP_WAIT(0);
        __syncthreads();
        int cn = c + 1;
        if (cn < NC) {
            int k0 = cn * BK1;
            uint32_t stg = sbase + (uint32_t)((cn & 1) * F2_STAGE * 4);
#pragma unroll
            for (int j = 0; j < 2; j++) {
                CP16(stg + tdst[j], asrc[j] + k0);
                CP16(stg + T1W * 4 + tdst[j], bsrc[j] + k0);
            }
        }
        CP_COMMIT();
        uint32_t Ab = sbase + (uint32_t)((c & 1) * F2_STAGE * 4);
        uint32_t Bb = Ab + T1W * 4;
#pragma unroll
        for (int s = 0; s < 4; s++) {
            uint32_t so = (uint32_t)(s * 32);
            uint32_t a[2][4], bf[2][4];
#pragma unroll
            for (int mi = 0; mi < 2; mi++)
                ldsm4(a[mi], Ab + a_off + (uint32_t)(mi * 16 * T1ROWB) + so);
#pragma unroll
            for (int pi = 0; pi < 2; pi++)
                ldsm4(bf[pi], Bb + b_off + (uint32_t)(pi * 16 * T1ROWB) + so);
#pragma unroll
            for (int pi = 0; pi < 2; pi++) {
#pragma unroll
                for (int h = 0; h < 2; h++) {
                    int ni = 2 * pi + h;
                    mma16(ca[0][ni], a[0], bf[pi][2 * h], bf[pi][2 * h + 1]);
                    mma16(ca[1][ni], a[1], bf[pi][2 * h], bf[pi][2 * h + 1]);
                }
            }
        }
    }

    // epilogue: deterministic atomic combine
    const float* dpb = dp_b + e * DM;
    int lr = wm * 32 + (lane >> 2);
    int cbase = wn * 32 + 2 * (lane & 3);
#pragma unroll
    for (int ni = 0; ni < 4; ni++) {
        int col = n0 + cbase + ni * 8;
        float b0v = dpb[col], b1v = dpb[col + 1];
#pragma unroll
        for (int mi = 0; mi < 2; mi++) {
            int l0 = lr + mi * 16;
            int t0 = s_toks[l0];
            if (t0 >= 0) {
                float w = s_wts[l0];
                atomicAdd(out + (size_t)t0 * DM + col,     w * (ca[mi][ni][0] + b0v));
                atomicAdd(out + (size_t)t0 * DM + col + 1, w * (ca[mi][ni][1] + b1v));
            }
            int t1 = s_toks[l0 + 8];
            if (t1 >= 0) {
                float w = s_wts[l0 + 8];
                atomicAdd(out + (size_t)t1 * DM + col,     w * (ca[mi][ni][2] + b0v));
                atomicAdd(out + (size_t)t1 * DM + col + 1, w * (ca[mi][ni][3] + b1v));
            }
        }
    }
}

// ---------------- launcher ----------------
extern "C" void kernel_launch(void* const* d_in, const int* in_sizes, int n_in,
                              void* d_out, int out_size) {
    const float* x   = (const float*)d_in[0];
    const float* gw  = (const float*)d_in[1];
    const float* gb  = (const float*)d_in[2];
    const float* gpw = (const float*)d_in[3];
    const float* gpb = (const float*)d_in[4];
    const float* upw = (const float*)d_in[5];
    const float* upb = (const float*)d_in[6];
    const float* dpw = (const float*)d_in[7];
    const float* dpb = (const float*)d_in[8];
    float* out = (float*)d_out;

    static int init_done = 0;
    static cudaStream_t s2;
    static cudaEvent_t ev_fork, ev_join;
    if (!init_done) {
        cudaFuncSetAttribute(ffn1_mma, cudaFuncAttributeMaxDynamicSharedMemorySize,
                             F1_SMEM);
        cudaFuncSetAttribute(ffn2_mma, cudaFuncAttributeMaxDynamicSharedMemorySize,
                             F2_SMEM);
        cudaStreamCreateWithFlags(&s2, cudaStreamNonBlocking);
        cudaEventCreateWithFlags(&ev_fork, cudaEventDisableTiming);
        cudaEventCreateWithFlags(&ev_join, cudaEventDisableTiming);
        init_done = 1;
    }

    // fork: weight conversion + output zeroing run concurrently with routing
    cudaEventRecord(ev_fork, 0);
    cudaStreamWaitEvent(s2, ev_fork, 0);
    convert_weights<<<dim3(32, 32, 3 * NE), dim3(32, 8), 0, s2>>>(gpw, upw, dpw);
    zero_kernel<<<1024, 256, 0, s2>>>(out, (long)out_size);
    cudaEventRecord(ev_join, s2);

    // main: routing chain
    init_kernel<<<1, 32>>>();
    gate_kernel<<<(T_TOK / 4 * 32 + 255) / 256, 256>>>(x, gw, gb);
    scan_kernel<<<1, 1>>>();
    scatter_kernel<<<(T_TOK + 255) / 256, 256>>>();
    pad_kernel<<<(PAD_ROWS + 255) / 256, 256>>>();

    // join, then aux (writes out[TD], must follow zero) and FFN
    cudaStreamWaitEvent(0, ev_join, 0);
    aux_kernel<<<1, 32>>>(out, (long)out_size);

    ffn1_mma<<<dim3(MTILES, HID / BNT), 512, F1_SMEM>>>(gpb, upb);
    ffn2_mma<<<dim3(MTILES, DM / BNT), 512, F2_SMEM>>>(dpb, out);
}